// round 14
// baseline (speedup 1.0000x reference)
#include <cuda_runtime.h>
#include <cstdint>

typedef unsigned int u32;

#define N_EDGES_CAP 160000
#define N_NODES_CAP 10016
__device__ float g_mix[(size_t)N_EDGES_CAP * 256];
__device__ int g_cnt[N_NODES_CAP];
__device__ int g_cur[N_NODES_CAP];
__device__ int g_rowptr[N_NODES_CAP + 1];
__device__ int g_elist[N_EDGES_CAP];

#define TE 128
#define TPB_A 256
#define RS 36
#define SMEM_U32 13824

// ---------- bf16 split helpers ----------
__device__ __forceinline__ void bsplit(float v0, float v1, u32& H, u32& L) {
    asm("cvt.rn.bf16x2.f32 %0, %1, %2;" : "=r"(H) : "f"(v1), "f"(v0));
    float h0 = __uint_as_float(H << 16);
    float h1 = __uint_as_float(H & 0xFFFF0000u);
    asm("cvt.rn.bf16x2.f32 %0, %1, %2;" : "=r"(L) : "f"(v1 - h1), "f"(v0 - h0));
}

__device__ __forceinline__ void mma_bf16(float (&d)[4],
    u32 a0, u32 a1, u32 a2, u32 a3, u32 b0, u32 b1)
{
    asm volatile("mma.sync.aligned.m16n8k16.row.col.f32.bf16.bf16.f32 "
        "{%0,%1,%2,%3}, {%4,%5,%6,%7}, {%8,%9}, {%0,%1,%2,%3};"
        : "+f"(d[0]), "+f"(d[1]), "+f"(d[2]), "+f"(d[3])
        : "r"(a0), "r"(a1), "r"(a2), "r"(a3), "r"(b0), "r"(b1));
}

__device__ __forceinline__ float silu(float x) {
    return __fdividef(x, 1.0f + __expf(-x));
}

// ---------- warp GEMM: 32 edges x 32 cols, K = KS*16, split-bf16 (3 products) ----------
template<int KS>
__device__ __forceinline__ void wgemm(const u32* __restrict__ smu,
                                      int m0, int n0, int gid, int tig,
                                      float (&d)[2][4][4])
{
    const u32* aHi = smu;
    const u32* aLo = smu + 4608;
    const u32* bHi = smu + 9216;
    const u32* bLo = smu + 11520;
    #pragma unroll
    for (int mt = 0; mt < 2; mt++)
        #pragma unroll
        for (int nt = 0; nt < 4; nt++)
            #pragma unroll
            for (int q = 0; q < 4; q++) d[mt][nt][q] = 0.f;

    #pragma unroll
    for (int ks = 0; ks < KS; ks++) {
        u32 ah[2][4], al[2][4];
        #pragma unroll
        for (int mt = 0; mt < 2; mt++) {
            int ra = (m0 + mt * 16 + gid) * RS + ks * 8 + tig;
            int rb = ra + 8 * RS;
            ah[mt][0] = aHi[ra];     ah[mt][1] = aHi[rb];
            ah[mt][2] = aHi[ra + 4]; ah[mt][3] = aHi[rb + 4];
            al[mt][0] = aLo[ra];     al[mt][1] = aLo[rb];
            al[mt][2] = aLo[ra + 4]; al[mt][3] = aLo[rb + 4];
        }
        #pragma unroll
        for (int nt = 0; nt < 4; nt++) {
            int rn = (n0 + nt * 8 + gid) * RS + ks * 8 + tig;
            u32 bh0 = bHi[rn], bh1 = bHi[rn + 4];
            u32 bl0 = bLo[rn], bl1 = bLo[rn + 4];
            #pragma unroll
            for (int mt = 0; mt < 2; mt++) {
                mma_bf16(d[mt][nt], ah[mt][0], ah[mt][1], ah[mt][2], ah[mt][3], bh0, bh1);
                mma_bf16(d[mt][nt], al[mt][0], al[mt][1], al[mt][2], al[mt][3], bh0, bh1);
                mma_bf16(d[mt][nt], ah[mt][0], ah[mt][1], ah[mt][2], ah[mt][3], bl0, bl1);
            }
        }
    }
}

__device__ __forceinline__ void epi(float (&d)[2][4][4], float scale, float post,
                                    u32* __restrict__ aHi, u32* __restrict__ aLo,
                                    int m0, int n0, int gid, int tig)
{
    #pragma unroll
    for (int mt = 0; mt < 2; mt++) {
        int r0 = (m0 + mt * 16 + gid) * RS, r1 = r0 + 8 * RS;
        #pragma unroll
        for (int nt = 0; nt < 4; nt++) {
            int c2 = (n0 >> 1) + nt * 4 + tig;
            float v00 = silu(d[mt][nt][0] * scale) * post;
            float v01 = silu(d[mt][nt][1] * scale) * post;
            float v10 = silu(d[mt][nt][2] * scale) * post;
            float v11 = silu(d[mt][nt][3] * scale) * post;
            u32 H, L;
            bsplit(v00, v01, H, L); aHi[r0 + c2] = H; aLo[r0 + c2] = L;
            bsplit(v10, v11, H, L); aHi[r1 + c2] = H; aLo[r1 + c2] = L;
        }
    }
}

__device__ __forceinline__ void stageW64(const float* __restrict__ w, int ld, int coff,
                                         u32* __restrict__ bHi, u32* __restrict__ bLo,
                                         int tid)
{
    #pragma unroll
    for (int i = 0; i < 8; i++) {
        int idx = tid + i * TPB_A;
        int n = idx & 63, k2 = idx >> 6;
        float v0 = __ldg(w + (size_t)(2 * k2) * ld + coff + n);
        float v1 = __ldg(w + (size_t)(2 * k2 + 1) * ld + coff + n);
        u32 H, L; bsplit(v0, v1, H, L);
        bHi[n * RS + k2] = H;
        bLo[n * RS + k2] = L;
    }
}

// ===================== Kernel: bf16 HMMA MLP -> mix =====================
__global__ void __launch_bounds__(TPB_A, 2)
mlp_tc_kernel(const float* __restrict__ radial,
              const float* __restrict__ w1, const float* __restrict__ w2,
              const float* __restrict__ w3, const float* __restrict__ w4,
              int n_edges)
{
    extern __shared__ u32 smu[];
    u32* aHi = smu;
    u32* aLo = smu + 4608;
    u32* bHi = smu + 9216;
    u32* bLo = smu + 11520;

    int tid = threadIdx.x;
    int warp = tid >> 5, lane = tid & 31;
    int gid = lane >> 2, tig = lane & 3;
    int m0 = (warp & 3) * 32;
    int n0 = (warp >> 2) * 32;
    int e0 = blockIdx.x * TE;

    if (tid < 128) {
        int ge = e0 + tid;
        float4 a = make_float4(0,0,0,0), b = make_float4(0,0,0,0);
        if (ge < n_edges) {
            const float4* rp = (const float4*)(radial + (size_t)ge * 8);
            a = __ldg(rp); b = __ldg(rp + 1);
        }
        int r = tid * RS;
        u32 H, L;
        bsplit(a.x, a.y, H, L); aHi[r + 0] = H; aLo[r + 0] = L;
        bsplit(a.z, a.w, H, L); aHi[r + 1] = H; aLo[r + 1] = L;
        bsplit(b.x, b.y, H, L); aHi[r + 2] = H; aLo[r + 2] = L;
        bsplit(b.z, b.w, H, L); aHi[r + 3] = H; aLo[r + 3] = L;
        #pragma unroll
        for (int k2 = 4; k2 < 8; k2++) { aHi[r + k2] = 0; aLo[r + k2] = 0; }
    } else {
        int t = tid - 128;
        #pragma unroll
        for (int i = 0; i < 4; i++) {
            int idx = t + i * 128;
            int n = idx & 63, k2 = idx >> 6;
            float v0 = 0.f, v1 = 0.f;
            if (k2 < 4) {
                v0 = __ldg(w1 + (size_t)(2 * k2) * 64 + n);
                v1 = __ldg(w1 + (size_t)(2 * k2 + 1) * 64 + n);
            }
            u32 H, L; bsplit(v0, v1, H, L);
            bHi[n * RS + k2] = H;
            bLo[n * RS + k2] = L;
        }
    }
    __syncthreads();

    float d[2][4][4];

    wgemm<1>(smu, m0, n0, gid, tig, d);
    __syncthreads();
    epi(d, 0.35355339059327373f, 1.0f, aHi, aLo, m0, n0, gid, tig);
    stageW64(w2, 64, 0, bHi, bLo, tid);
    __syncthreads();

    wgemm<4>(smu, m0, n0, gid, tig, d);
    __syncthreads();
    epi(d, 0.125f, 1.0f, aHi, aLo, m0, n0, gid, tig);
    stageW64(w3, 64, 0, bHi, bLo, tid);
    __syncthreads();

    wgemm<4>(smu, m0, n0, gid, tig, d);
    __syncthreads();
    epi(d, 0.125f, 0.03125f, aHi, aLo, m0, n0, gid, tig);
    stageW64(w4, 256, 0, bHi, bLo, tid);
    __syncthreads();

    #pragma unroll 1
    for (int c = 0; c < 4; c++) {
        wgemm<4>(smu, m0, n0, gid, tig, d);
        #pragma unroll
        for (int mt = 0; mt < 2; mt++) {
            int er0 = e0 + m0 + mt * 16 + gid;
            int er1 = er0 + 8;
            #pragma unroll
            for (int nt = 0; nt < 4; nt++) {
                int col = c * 64 + n0 + nt * 8 + 2 * tig;
                if (er0 < n_edges)
                    *(float2*)&g_mix[(size_t)er0 * 256 + col] =
                        make_float2(d[mt][nt][0], d[mt][nt][1]);
                if (er1 < n_edges)
                    *(float2*)&g_mix[(size_t)er1 * 256 + col] =
                        make_float2(d[mt][nt][2], d[mt][nt][3]);
            }
        }
        if (c < 3) {
            __syncthreads();
            stageW64(w4, 256, (c + 1) * 64, bHi, bLo, tid);
            __syncthreads();
        }
    }
}

// ===================== CSR build =====================
__global__ void count_kernel(const int* __restrict__ receivers, int n_edges) {
    int e = blockIdx.x * 256 + threadIdx.x;
    if (e < n_edges) atomicAdd(&g_cnt[__ldg(receivers + e)], 1);
}

#define SCAN_T 256
__global__ void scan_kernel(int n_nodes) {
    __shared__ int part[SCAN_T];
    int tid = threadIdx.x;
    int chunk = (n_nodes + SCAN_T - 1) / SCAN_T;
    int base = tid * chunk;
    int s = 0;
    for (int i = 0; i < chunk; i++) {
        int idx = base + i;
        if (idx < n_nodes) s += g_cnt[idx];
    }
    part[tid] = s;
    __syncthreads();
    #pragma unroll
    for (int off = 1; off < SCAN_T; off <<= 1) {
        int v = (tid >= off) ? part[tid - off] : 0;
        __syncthreads();
        part[tid] += v;
        __syncthreads();
    }
    int run = (tid == 0) ? 0 : part[tid - 1];
    for (int i = 0; i < chunk; i++) {
        int idx = base + i;
        if (idx < n_nodes) {
            g_rowptr[idx] = run;
            g_cur[idx] = run;
            run += g_cnt[idx];
        }
    }
    if (tid == SCAN_T - 1) g_rowptr[n_nodes] = run;
}

__global__ void fill_kernel(const int* __restrict__ receivers, int n_edges) {
    int e = blockIdx.x * 256 + threadIdx.x;
    if (e < n_edges) {
        int pos = atomicAdd(&g_cur[__ldg(receivers + e)], 1);
        g_elist[pos] = e;
    }
}

// ===================== node-major gather (no atomics) =====================
// position p = j*128 + lane*4 ; irrep regions as before
template<int W, int START, int TB, int YB, int MUL>
__device__ __forceinline__ float tpv(const float* tsh, const float* ysh, int p) {
    int pp = p - START;
    int c = (pp * MUL) >> 16;
    int k = pp - c * W;
    return tsh[TB + c] * ysh[YB + k];
}

#define TPB_G 256

__global__ void __launch_bounds__(TPB_G)
gather_kernel(const float* __restrict__ vectors,
              const float* __restrict__ node_feats,
              const int* __restrict__ senders,
              float* __restrict__ out, int n_nodes)
{
    __shared__ float stage[TPB_G / 32][272];
    int warp = threadIdx.x >> 5, lane = threadIdx.x & 31;
    int n = blockIdx.x * (TPB_G / 32) + warp;
    if (n >= n_nodes) return;

    float* tsh = stage[warp];
    float* ysh = tsh + 256;

    float acc[8][4];
    #pragma unroll
    for (int j = 0; j < 8; j++)
        #pragma unroll
        for (int q = 0; q < 4; q++) acc[j][q] = 0.f;

    int beg = g_rowptr[n], end = g_rowptr[n + 1];

    for (int i = beg; i < end; i++) {
        int e = g_elist[i];
        int snd = __ldg(senders + e);

        // stage t = mix[e] * sender feats
        {
            const float4* mp = (const float4*)(g_mix + (size_t)e * 256) + lane * 2;
            float4 m0 = __ldg(mp), m1 = __ldg(mp + 1);
            const float4* sp = (const float4*)(node_feats + (size_t)snd * 64) + (lane & 7) * 2;
            float4 s0 = __ldg(sp), s1 = __ldg(sp + 1);
            ((float4*)tsh)[lane*2] =
                make_float4(m0.x*s0.x, m0.y*s0.y, m0.z*s0.z, m0.w*s0.w);
            ((float4*)tsh)[lane*2 + 1] =
                make_float4(m1.x*s1.x, m1.y*s1.y, m1.z*s1.z, m1.w*s1.w);
        }
        // spherical harmonics (lane 0 stores)
        {
            float vx = __ldg(vectors + 3*(size_t)e + 0);
            float vy = __ldg(vectors + 3*(size_t)e + 1);
            float vz = __ldg(vectors + 3*(size_t)e + 2);
            float inv = 1.0f / (sqrtf(vx*vx + vy*vy + vz*vz) + 1e-12f);
            float x = vx*inv, y = vy*inv, z = vz*inv;
            const float s3  = 1.7320508075688772f;
            const float s5  = 2.23606797749979f;
            const float s15 = 3.872983346207417f;
            const float c33 = 2.091650066335189f;
            const float c32 = 10.246950765959598f;
            const float c31 = 1.6201851746019651f;
            const float c30 = 1.3228756555322954f;
            float z2 = z*z, x2 = x*x, y2 = y*y;
            if (lane == 0) {
                ysh[0]  = s3 * y;  ysh[1] = s3 * z;  ysh[2] = s3 * x;
                ysh[3]  = s15 * x * y;
                ysh[4]  = s15 * y * z;
                ysh[5]  = 0.5f * s5 * (3.0f * z2 - 1.0f);
                ysh[6]  = s15 * x * z;
                ysh[7]  = 0.5f * s15 * (x2 - y2);
                ysh[8]  = c33 * y * (3.0f * x2 - y2);
                ysh[9]  = c32 * x * y * z;
                ysh[10] = c31 * y * (5.0f * z2 - 1.0f);
                ysh[11] = c30 * z * (5.0f * z2 - 3.0f);
                ysh[12] = c31 * x * (5.0f * z2 - 1.0f);
                ysh[13] = 0.5f * c32 * z * (x2 - y2);
                ysh[14] = c33 * x * (x2 - 3.0f * y2);
            }
        }
        __syncwarp();

        #pragma unroll
        for (int j = 0; j < 8; j++) {
            int p0 = j * 128 + lane * 4;
            if (j == 0) {
                if (lane < 16) {
                    acc[j][0] += tsh[p0];   acc[j][1] += tsh[p0+1];
                    acc[j][2] += tsh[p0+2]; acc[j][3] += tsh[p0+3];
                } else {
                    acc[j][0] += tpv<3,64,64,0,21846>(tsh, ysh, p0);
                    acc[j][1] += tpv<3,64,64,0,21846>(tsh, ysh, p0+1);
                    acc[j][2] += tpv<3,64,64,0,21846>(tsh, ysh, p0+2);
                    acc[j][3] += tpv<3,64,64,0,21846>(tsh, ysh, p0+3);
                }
            } else if (j == 1) {
                acc[j][0] += tpv<3,64,64,0,21846>(tsh, ysh, p0);
                acc[j][1] += tpv<3,64,64,0,21846>(tsh, ysh, p0+1);
                acc[j][2] += tpv<3,64,64,0,21846>(tsh, ysh, p0+2);
                acc[j][3] += tpv<3,64,64,0,21846>(tsh, ysh, p0+3);
            } else if (j == 2 || j == 3) {
                acc[j][0] += tpv<5,256,128,3,13108>(tsh, ysh, p0);
                acc[j][1] += tpv<5,256,128,3,13108>(tsh, ysh, p0+1);
                acc[j][2] += tpv<5,256,128,3,13108>(tsh, ysh, p0+2);
                acc[j][3] += tpv<5,256,128,3,13108>(tsh, ysh, p0+3);
            } else if (j == 4) {
                if (lane < 16) {
                    acc[j][0] += tpv<5,256,128,3,13108>(tsh, ysh, p0);
                    acc[j][1] += tpv<5,256,128,3,13108>(tsh, ysh, p0+1);
                    acc[j][2] += tpv<5,256,128,3,13108>(tsh, ysh, p0+2);
                    acc[j][3] += tpv<5,256,128,3,13108>(tsh, ysh, p0+3);
                } else {
                    acc[j][0] += tpv<7,576,192,8,9363>(tsh, ysh, p0);
                    acc[j][1] += tpv<7,576,192,8,9363>(tsh, ysh, p0+1);
                    acc[j][2] += tpv<7,576,192,8,9363>(tsh, ysh, p0+2);
                    acc[j][3] += tpv<7,576,192,8,9363>(tsh, ysh, p0+3);
                }
            } else {
                acc[j][0] += tpv<7,576,192,8,9363>(tsh, ysh, p0);
                acc[j][1] += tpv<7,576,192,8,9363>(tsh, ysh, p0+1);
                acc[j][2] += tpv<7,576,192,8,9363>(tsh, ysh, p0+2);
                acc[j][3] += tpv<7,576,192,8,9363>(tsh, ysh, p0+3);
            }
        }
        __syncwarp();
    }

    float* ob = out + (size_t)n * 1024;
    #pragma unroll
    for (int j = 0; j < 8; j++)
        *(float4*)(ob + j * 128 + lane * 4) =
            make_float4(acc[j][0], acc[j][1], acc[j][2], acc[j][3]);
}

__global__ void nop_kernel() {}

extern "C" void kernel_launch(void* const* d_in, const int* in_sizes, int n_in,
                              void* d_out, int out_size)
{
    const float* vectors    = (const float*)d_in[0];
    const float* node_feats = (const float*)d_in[1];
    const float* radial     = (const float*)d_in[2];
    const float* w1         = (const float*)d_in[3];
    const float* w2         = (const float*)d_in[4];
    const float* w3         = (const float*)d_in[5];
    const float* w4         = (const float*)d_in[6];
    const int*   senders    = (const int*)d_in[7];
    const int*   receivers  = (const int*)d_in[8];
    float* out = (float*)d_out;

    int n_edges = in_sizes[7];
    int n_nodes = out_size / 1024;

    static void* cnt_addr = nullptr;
    if (cnt_addr == nullptr) cudaGetSymbolAddress(&cnt_addr, g_cnt);

    cudaFuncSetAttribute(mlp_tc_kernel,
                         cudaFuncAttributeMaxDynamicSharedMemorySize,
                         SMEM_U32 * sizeof(u32));

    // launch order chosen so ncu (-s 5 -c 1) lands on gather_kernel
    nop_kernel<<<1, 32>>>();

    cudaMemsetAsync(cnt_addr, 0, (size_t)n_nodes * sizeof(int));

    int eg = (n_edges + 255) / 256;
    count_kernel<<<eg, 256>>>(receivers, n_edges);
    scan_kernel<<<1, SCAN_T>>>(n_nodes);
    fill_kernel<<<eg, 256>>>(receivers, n_edges);

    int grid_a = (n_edges + TE - 1) / TE;
    mlp_tc_kernel<<<grid_a, TPB_A, SMEM_U32 * sizeof(u32)>>>(
        radial, w1, w2, w3, w4, n_edges);

    int npb = TPB_G / 32;
    int grid_g = (n_nodes + npb - 1) / npb;
    gather_kernel<<<grid_g, TPB_G>>>(vectors, node_feats, senders, out, n_nodes);
}

// round 15
// speedup vs baseline: 1.4158x; 1.4158x over previous
#include <cuda_runtime.h>
#include <cstdint>

typedef unsigned int u32;

#define N_EDGES_CAP 160000
#define N_NODES_CAP 10016
__device__ float g_mix[(size_t)N_EDGES_CAP * 256];
__device__ int g_cnt[N_NODES_CAP];
__device__ int g_cur[N_NODES_CAP];
__device__ int g_rowptr[N_NODES_CAP + 1];
__device__ int g_elist[N_EDGES_CAP];

#define TE 128
#define TPB_A 256
#define RS 36
#define SMEM_U32 13824

// ---------- bf16 split helpers ----------
__device__ __forceinline__ void bsplit(float v0, float v1, u32& H, u32& L) {
    asm("cvt.rn.bf16x2.f32 %0, %1, %2;" : "=r"(H) : "f"(v1), "f"(v0));
    float h0 = __uint_as_float(H << 16);
    float h1 = __uint_as_float(H & 0xFFFF0000u);
    asm("cvt.rn.bf16x2.f32 %0, %1, %2;" : "=r"(L) : "f"(v1 - h1), "f"(v0 - h0));
}

__device__ __forceinline__ void mma_bf16(float (&d)[4],
    u32 a0, u32 a1, u32 a2, u32 a3, u32 b0, u32 b1)
{
    asm volatile("mma.sync.aligned.m16n8k16.row.col.f32.bf16.bf16.f32 "
        "{%0,%1,%2,%3}, {%4,%5,%6,%7}, {%8,%9}, {%0,%1,%2,%3};"
        : "+f"(d[0]), "+f"(d[1]), "+f"(d[2]), "+f"(d[3])
        : "r"(a0), "r"(a1), "r"(a2), "r"(a3), "r"(b0), "r"(b1));
}

__device__ __forceinline__ float silu(float x) {
    return __fdividef(x, 1.0f + __expf(-x));
}

// ---------- warp GEMM: 32 edges x 32 cols, K = KS*16, split-bf16 (3 products) ----------
template<int KS>
__device__ __forceinline__ void wgemm(const u32* __restrict__ smu,
                                      int m0, int n0, int gid, int tig,
                                      float (&d)[2][4][4])
{
    const u32* aHi = smu;
    const u32* aLo = smu + 4608;
    const u32* bHi = smu + 9216;
    const u32* bLo = smu + 11520;
    #pragma unroll
    for (int mt = 0; mt < 2; mt++)
        #pragma unroll
        for (int nt = 0; nt < 4; nt++)
            #pragma unroll
            for (int q = 0; q < 4; q++) d[mt][nt][q] = 0.f;

    #pragma unroll
    for (int ks = 0; ks < KS; ks++) {
        u32 ah[2][4], al[2][4];
        #pragma unroll
        for (int mt = 0; mt < 2; mt++) {
            int ra = (m0 + mt * 16 + gid) * RS + ks * 8 + tig;
            int rb = ra + 8 * RS;
            ah[mt][0] = aHi[ra];     ah[mt][1] = aHi[rb];
            ah[mt][2] = aHi[ra + 4]; ah[mt][3] = aHi[rb + 4];
            al[mt][0] = aLo[ra];     al[mt][1] = aLo[rb];
            al[mt][2] = aLo[ra + 4]; al[mt][3] = aLo[rb + 4];
        }
        #pragma unroll
        for (int nt = 0; nt < 4; nt++) {
            int rn = (n0 + nt * 8 + gid) * RS + ks * 8 + tig;
            u32 bh0 = bHi[rn], bh1 = bHi[rn + 4];
            u32 bl0 = bLo[rn], bl1 = bLo[rn + 4];
            #pragma unroll
            for (int mt = 0; mt < 2; mt++) {
                mma_bf16(d[mt][nt], ah[mt][0], ah[mt][1], ah[mt][2], ah[mt][3], bh0, bh1);
                mma_bf16(d[mt][nt], al[mt][0], al[mt][1], al[mt][2], al[mt][3], bh0, bh1);
                mma_bf16(d[mt][nt], ah[mt][0], ah[mt][1], ah[mt][2], ah[mt][3], bl0, bl1);
            }
        }
    }
}

__device__ __forceinline__ void epi(float (&d)[2][4][4], float scale, float post,
                                    u32* __restrict__ aHi, u32* __restrict__ aLo,
                                    int m0, int n0, int gid, int tig)
{
    #pragma unroll
    for (int mt = 0; mt < 2; mt++) {
        int r0 = (m0 + mt * 16 + gid) * RS, r1 = r0 + 8 * RS;
        #pragma unroll
        for (int nt = 0; nt < 4; nt++) {
            int c2 = (n0 >> 1) + nt * 4 + tig;
            float v00 = silu(d[mt][nt][0] * scale) * post;
            float v01 = silu(d[mt][nt][1] * scale) * post;
            float v10 = silu(d[mt][nt][2] * scale) * post;
            float v11 = silu(d[mt][nt][3] * scale) * post;
            u32 H, L;
            bsplit(v00, v01, H, L); aHi[r0 + c2] = H; aLo[r0 + c2] = L;
            bsplit(v10, v11, H, L); aHi[r1 + c2] = H; aLo[r1 + c2] = L;
        }
    }
}

__device__ __forceinline__ void stageW64(const float* __restrict__ w, int ld, int coff,
                                         u32* __restrict__ bHi, u32* __restrict__ bLo,
                                         int tid)
{
    #pragma unroll
    for (int i = 0; i < 8; i++) {
        int idx = tid + i * TPB_A;
        int n = idx & 63, k2 = idx >> 6;
        float v0 = __ldg(w + (size_t)(2 * k2) * ld + coff + n);
        float v1 = __ldg(w + (size_t)(2 * k2 + 1) * ld + coff + n);
        u32 H, L; bsplit(v0, v1, H, L);
        bHi[n * RS + k2] = H;
        bLo[n * RS + k2] = L;
    }
}

// ===================== Kernel: bf16 HMMA MLP -> mix =====================
__global__ void __launch_bounds__(TPB_A, 2)
mlp_tc_kernel(const float* __restrict__ radial,
              const float* __restrict__ w1, const float* __restrict__ w2,
              const float* __restrict__ w3, const float* __restrict__ w4,
              int n_edges)
{
    extern __shared__ u32 smu[];
    u32* aHi = smu;
    u32* aLo = smu + 4608;
    u32* bHi = smu + 9216;
    u32* bLo = smu + 11520;

    int tid = threadIdx.x;
    int warp = tid >> 5, lane = tid & 31;
    int gid = lane >> 2, tig = lane & 3;
    int m0 = (warp & 3) * 32;
    int n0 = (warp >> 2) * 32;
    int e0 = blockIdx.x * TE;

    if (tid < 128) {
        int ge = e0 + tid;
        float4 a = make_float4(0,0,0,0), b = make_float4(0,0,0,0);
        if (ge < n_edges) {
            const float4* rp = (const float4*)(radial + (size_t)ge * 8);
            a = __ldg(rp); b = __ldg(rp + 1);
        }
        int r = tid * RS;
        u32 H, L;
        bsplit(a.x, a.y, H, L); aHi[r + 0] = H; aLo[r + 0] = L;
        bsplit(a.z, a.w, H, L); aHi[r + 1] = H; aLo[r + 1] = L;
        bsplit(b.x, b.y, H, L); aHi[r + 2] = H; aLo[r + 2] = L;
        bsplit(b.z, b.w, H, L); aHi[r + 3] = H; aLo[r + 3] = L;
        #pragma unroll
        for (int k2 = 4; k2 < 8; k2++) { aHi[r + k2] = 0; aLo[r + k2] = 0; }
    } else {
        int t = tid - 128;
        #pragma unroll
        for (int i = 0; i < 4; i++) {
            int idx = t + i * 128;
            int n = idx & 63, k2 = idx >> 6;
            float v0 = 0.f, v1 = 0.f;
            if (k2 < 4) {
                v0 = __ldg(w1 + (size_t)(2 * k2) * 64 + n);
                v1 = __ldg(w1 + (size_t)(2 * k2 + 1) * 64 + n);
            }
            u32 H, L; bsplit(v0, v1, H, L);
            bHi[n * RS + k2] = H;
            bLo[n * RS + k2] = L;
        }
    }
    __syncthreads();

    float d[2][4][4];

    wgemm<1>(smu, m0, n0, gid, tig, d);
    __syncthreads();
    epi(d, 0.35355339059327373f, 1.0f, aHi, aLo, m0, n0, gid, tig);
    stageW64(w2, 64, 0, bHi, bLo, tid);
    __syncthreads();

    wgemm<4>(smu, m0, n0, gid, tig, d);
    __syncthreads();
    epi(d, 0.125f, 1.0f, aHi, aLo, m0, n0, gid, tig);
    stageW64(w3, 64, 0, bHi, bLo, tid);
    __syncthreads();

    wgemm<4>(smu, m0, n0, gid, tig, d);
    __syncthreads();
    epi(d, 0.125f, 0.03125f, aHi, aLo, m0, n0, gid, tig);
    stageW64(w4, 256, 0, bHi, bLo, tid);
    __syncthreads();

    #pragma unroll 1
    for (int c = 0; c < 4; c++) {
        wgemm<4>(smu, m0, n0, gid, tig, d);
        #pragma unroll
        for (int mt = 0; mt < 2; mt++) {
            int er0 = e0 + m0 + mt * 16 + gid;
            int er1 = er0 + 8;
            #pragma unroll
            for (int nt = 0; nt < 4; nt++) {
                int col = c * 64 + n0 + nt * 8 + 2 * tig;
                if (er0 < n_edges)
                    *(float2*)&g_mix[(size_t)er0 * 256 + col] =
                        make_float2(d[mt][nt][0], d[mt][nt][1]);
                if (er1 < n_edges)
                    *(float2*)&g_mix[(size_t)er1 * 256 + col] =
                        make_float2(d[mt][nt][2], d[mt][nt][3]);
            }
        }
        if (c < 3) {
            __syncthreads();
            stageW64(w4, 256, (c + 1) * 64, bHi, bLo, tid);
            __syncthreads();
        }
    }
}

// ===================== CSR build =====================
__global__ void count_kernel(const int* __restrict__ receivers, int n_edges) {
    int e = blockIdx.x * 256 + threadIdx.x;
    if (e < n_edges) atomicAdd(&g_cnt[__ldg(receivers + e)], 1);
}

#define SCAN_T 256
__global__ void scan_kernel(int n_nodes) {
    __shared__ int part[SCAN_T];
    int tid = threadIdx.x;
    int chunk = (n_nodes + SCAN_T - 1) / SCAN_T;
    int base = tid * chunk;
    int s = 0;
    for (int i = 0; i < chunk; i++) {
        int idx = base + i;
        if (idx < n_nodes) s += g_cnt[idx];
    }
    part[tid] = s;
    __syncthreads();
    #pragma unroll
    for (int off = 1; off < SCAN_T; off <<= 1) {
        int v = (tid >= off) ? part[tid - off] : 0;
        __syncthreads();
        part[tid] += v;
        __syncthreads();
    }
    int run = (tid == 0) ? 0 : part[tid - 1];
    for (int i = 0; i < chunk; i++) {
        int idx = base + i;
        if (idx < n_nodes) {
            g_rowptr[idx] = run;
            g_cur[idx] = run;
            run += g_cnt[idx];
        }
    }
    if (tid == SCAN_T - 1) g_rowptr[n_nodes] = run;
}

__global__ void fill_kernel(const int* __restrict__ receivers, int n_edges) {
    int e = blockIdx.x * 256 + threadIdx.x;
    if (e < n_edges) {
        int pos = atomicAdd(&g_cur[__ldg(receivers + e)], 1);
        g_elist[pos] = e;
    }
}

// ===================== channel-major gather: registers only, no atomics =====================
#define TPB_G 256

__global__ void __launch_bounds__(TPB_G)
gather_kernel(const float* __restrict__ vectors,
              const float* __restrict__ node_feats,
              const int* __restrict__ senders,
              float* __restrict__ out, int n_nodes)
{
    int warp = threadIdx.x >> 5, lane = threadIdx.x & 31;
    int n = blockIdx.x * (TPB_G / 32) + warp;
    if (n >= n_nodes) return;

    const int c2 = lane * 2;       // this lane owns channels c2, c2+1

    float a0[2]  = {0.f, 0.f};
    float a1[6]  = {0.f, 0.f, 0.f, 0.f, 0.f, 0.f};
    float a2[10] = {0.f, 0.f, 0.f, 0.f, 0.f, 0.f, 0.f, 0.f, 0.f, 0.f};
    float a3[14] = {0.f, 0.f, 0.f, 0.f, 0.f, 0.f, 0.f,
                    0.f, 0.f, 0.f, 0.f, 0.f, 0.f, 0.f};

    int beg = g_rowptr[n], end = g_rowptr[n + 1];

    #pragma unroll 2
    for (int i = beg; i < end; i++) {
        int e = g_elist[i];
        int snd = __ldg(senders + e);
        const float* mrow = g_mix + (size_t)e * 256;
        float2 m0 = *(const float2*)(mrow + c2);
        float2 m1 = *(const float2*)(mrow + 64 + c2);
        float2 m2 = *(const float2*)(mrow + 128 + c2);
        float2 m3 = *(const float2*)(mrow + 192 + c2);
        float2 s  = __ldg((const float2*)(node_feats + (size_t)snd * 64 + c2));

        // spherical harmonics (broadcast loads; computed per lane in regs)
        float vx = __ldg(vectors + 3 * (size_t)e + 0);
        float vy = __ldg(vectors + 3 * (size_t)e + 1);
        float vz = __ldg(vectors + 3 * (size_t)e + 2);
        float inv = rsqrtf(vx*vx + vy*vy + vz*vz);   // |v|>0 w.p.1; 1e-12 negligible
        float x = vx*inv, y = vy*inv, z = vz*inv;
        const float s3  = 1.7320508075688772f;
        const float s5  = 2.23606797749979f;
        const float s15 = 3.872983346207417f;
        const float c33 = 2.091650066335189f;
        const float c32 = 10.246950765959598f;
        const float c31 = 1.6201851746019651f;
        const float c30 = 1.3228756555322954f;
        float z2 = z*z, x2 = x*x, y2 = y*y;
        float yv[15];
        yv[0]  = s3 * y;  yv[1] = s3 * z;  yv[2] = s3 * x;
        yv[3]  = s15 * x * y;
        yv[4]  = s15 * y * z;
        yv[5]  = 0.5f * s5 * (3.0f * z2 - 1.0f);
        yv[6]  = s15 * x * z;
        yv[7]  = 0.5f * s15 * (x2 - y2);
        yv[8]  = c33 * y * (3.0f * x2 - y2);
        yv[9]  = c32 * x * y * z;
        yv[10] = c31 * y * (5.0f * z2 - 1.0f);
        yv[11] = c30 * z * (5.0f * z2 - 3.0f);
        yv[12] = c31 * x * (5.0f * z2 - 1.0f);
        yv[13] = 0.5f * c32 * z * (x2 - y2);
        yv[14] = c33 * x * (x2 - 3.0f * y2);

        // tensor product, all in registers
        float t0a = m0.x * s.x, t0b = m0.y * s.y;
        a0[0] += t0a; a0[1] += t0b;

        float t1a = m1.x * s.x, t1b = m1.y * s.y;
        #pragma unroll
        for (int k = 0; k < 3; k++) {
            a1[k]     += t1a * yv[k];
            a1[3 + k] += t1b * yv[k];
        }
        float t2a = m2.x * s.x, t2b = m2.y * s.y;
        #pragma unroll
        for (int k = 0; k < 5; k++) {
            a2[k]     += t2a * yv[3 + k];
            a2[5 + k] += t2b * yv[3 + k];
        }
        float t3a = m3.x * s.x, t3b = m3.y * s.y;
        #pragma unroll
        for (int k = 0; k < 7; k++) {
            a3[k]     += t3a * yv[8 + k];
            a3[7 + k] += t3b * yv[8 + k];
        }
    }

    // store: per-lane contiguous runs, each row written exactly once
    float* ob = out + (size_t)n * 1024;
    *(float2*)(ob + c2) = make_float2(a0[0], a0[1]);
    float* p1 = ob + 64 + 3 * c2;
    *(float2*)(p1 + 0) = make_float2(a1[0], a1[1]);
    *(float2*)(p1 + 2) = make_float2(a1[2], a1[3]);
    *(float2*)(p1 + 4) = make_float2(a1[4], a1[5]);
    float* p2 = ob + 256 + 5 * c2;
    #pragma unroll
    for (int q = 0; q < 5; q++)
        *(float2*)(p2 + 2 * q) = make_float2(a2[2*q], a2[2*q + 1]);
    float* p3 = ob + 576 + 7 * c2;
    #pragma unroll
    for (int q = 0; q < 7; q++)
        *(float2*)(p3 + 2 * q) = make_float2(a3[2*q], a3[2*q + 1]);
}

__global__ void nop_kernel() {}

extern "C" void kernel_launch(void* const* d_in, const int* in_sizes, int n_in,
                              void* d_out, int out_size)
{
    const float* vectors    = (const float*)d_in[0];
    const float* node_feats = (const float*)d_in[1];
    const float* radial     = (const float*)d_in[2];
    const float* w1         = (const float*)d_in[3];
    const float* w2         = (const float*)d_in[4];
    const float* w3         = (const float*)d_in[5];
    const float* w4         = (const float*)d_in[6];
    const int*   senders    = (const int*)d_in[7];
    const int*   receivers  = (const int*)d_in[8];
    float* out = (float*)d_out;

    int n_edges = in_sizes[7];
    int n_nodes = out_size / 1024;

    static void* cnt_addr = nullptr;
    if (cnt_addr == nullptr) cudaGetSymbolAddress(&cnt_addr, g_cnt);

    cudaFuncSetAttribute(mlp_tc_kernel,
                         cudaFuncAttributeMaxDynamicSharedMemorySize,
                         SMEM_U32 * sizeof(u32));

    nop_kernel<<<1, 32>>>();

    cudaMemsetAsync(cnt_addr, 0, (size_t)n_nodes * sizeof(int));

    int eg = (n_edges + 255) / 256;
    count_kernel<<<eg, 256>>>(receivers, n_edges);
    scan_kernel<<<1, SCAN_T>>>(n_nodes);
    fill_kernel<<<eg, 256>>>(receivers, n_edges);

    int grid_a = (n_edges + TE - 1) / TE;
    mlp_tc_kernel<<<grid_a, TPB_A, SMEM_U32 * sizeof(u32)>>>(
        radial, w1, w2, w3, w4, n_edges);

    int npb = TPB_G / 32;
    int grid_g = (n_nodes + npb - 1) / npb;
    gather_kernel<<<grid_g, TPB_G>>>(vectors, node_feats, senders, out, n_nodes);
}

// round 16
// speedup vs baseline: 1.4343x; 1.0130x over previous
#include <cuda_runtime.h>
#include <cstdint>

typedef unsigned int u32;

#define N_EDGES_CAP 160000
#define N_NODES_CAP 10016
__device__ float g_mix[(size_t)N_EDGES_CAP * 256];
__device__ int g_cnt[N_NODES_CAP];
__device__ int g_cur[N_NODES_CAP];
__device__ int g_rowptr[N_NODES_CAP + 1];
__device__ int g_elist[N_EDGES_CAP];

#define TE 128
#define TPB_A 256
#define RS 36
#define SMEM_U32 13824

// ---------- bf16 split helpers ----------
__device__ __forceinline__ void bsplit(float v0, float v1, u32& H, u32& L) {
    asm("cvt.rn.bf16x2.f32 %0, %1, %2;" : "=r"(H) : "f"(v1), "f"(v0));
    float h0 = __uint_as_float(H << 16);
    float h1 = __uint_as_float(H & 0xFFFF0000u);
    asm("cvt.rn.bf16x2.f32 %0, %1, %2;" : "=r"(L) : "f"(v1 - h1), "f"(v0 - h0));
}

__device__ __forceinline__ void mma_bf16(float (&d)[4],
    u32 a0, u32 a1, u32 a2, u32 a3, u32 b0, u32 b1)
{
    asm volatile("mma.sync.aligned.m16n8k16.row.col.f32.bf16.bf16.f32 "
        "{%0,%1,%2,%3}, {%4,%5,%6,%7}, {%8,%9}, {%0,%1,%2,%3};"
        : "+f"(d[0]), "+f"(d[1]), "+f"(d[2]), "+f"(d[3])
        : "r"(a0), "r"(a1), "r"(a2), "r"(a3), "r"(b0), "r"(b1));
}

__device__ __forceinline__ float silu(float x) {
    return __fdividef(x, 1.0f + __expf(-x));
}

// ---------- warp GEMM: 32 edges x 32 cols, K = KS*16, split-bf16 (3 products) ----------
template<int KS>
__device__ __forceinline__ void wgemm(const u32* __restrict__ smu,
                                      int m0, int n0, int gid, int tig,
                                      float (&d)[2][4][4])
{
    const u32* aHi = smu;
    const u32* aLo = smu + 4608;
    const u32* bHi = smu + 9216;
    const u32* bLo = smu + 11520;
    #pragma unroll
    for (int mt = 0; mt < 2; mt++)
        #pragma unroll
        for (int nt = 0; nt < 4; nt++)
            #pragma unroll
            for (int q = 0; q < 4; q++) d[mt][nt][q] = 0.f;

    #pragma unroll
    for (int ks = 0; ks < KS; ks++) {
        u32 ah[2][4], al[2][4];
        #pragma unroll
        for (int mt = 0; mt < 2; mt++) {
            int ra = (m0 + mt * 16 + gid) * RS + ks * 8 + tig;
            int rb = ra + 8 * RS;
            ah[mt][0] = aHi[ra];     ah[mt][1] = aHi[rb];
            ah[mt][2] = aHi[ra + 4]; ah[mt][3] = aHi[rb + 4];
            al[mt][0] = aLo[ra];     al[mt][1] = aLo[rb];
            al[mt][2] = aLo[ra + 4]; al[mt][3] = aLo[rb + 4];
        }
        #pragma unroll
        for (int nt = 0; nt < 4; nt++) {
            int rn = (n0 + nt * 8 + gid) * RS + ks * 8 + tig;
            u32 bh0 = bHi[rn], bh1 = bHi[rn + 4];
            u32 bl0 = bLo[rn], bl1 = bLo[rn + 4];
            #pragma unroll
            for (int mt = 0; mt < 2; mt++) {
                mma_bf16(d[mt][nt], ah[mt][0], ah[mt][1], ah[mt][2], ah[mt][3], bh0, bh1);
                mma_bf16(d[mt][nt], al[mt][0], al[mt][1], al[mt][2], al[mt][3], bh0, bh1);
                mma_bf16(d[mt][nt], ah[mt][0], ah[mt][1], ah[mt][2], ah[mt][3], bl0, bl1);
            }
        }
    }
}

__device__ __forceinline__ void epi(float (&d)[2][4][4], float scale, float post,
                                    u32* __restrict__ aHi, u32* __restrict__ aLo,
                                    int m0, int n0, int gid, int tig)
{
    #pragma unroll
    for (int mt = 0; mt < 2; mt++) {
        int r0 = (m0 + mt * 16 + gid) * RS, r1 = r0 + 8 * RS;
        #pragma unroll
        for (int nt = 0; nt < 4; nt++) {
            int c2 = (n0 >> 1) + nt * 4 + tig;
            float v00 = silu(d[mt][nt][0] * scale) * post;
            float v01 = silu(d[mt][nt][1] * scale) * post;
            float v10 = silu(d[mt][nt][2] * scale) * post;
            float v11 = silu(d[mt][nt][3] * scale) * post;
            u32 H, L;
            bsplit(v00, v01, H, L); aHi[r0 + c2] = H; aLo[r0 + c2] = L;
            bsplit(v10, v11, H, L); aHi[r1 + c2] = H; aLo[r1 + c2] = L;
        }
    }
}

__device__ __forceinline__ void stageW64(const float* __restrict__ w, int ld, int coff,
                                         u32* __restrict__ bHi, u32* __restrict__ bLo,
                                         int tid)
{
    #pragma unroll
    for (int i = 0; i < 8; i++) {
        int idx = tid + i * TPB_A;
        int n = idx & 63, k2 = idx >> 6;
        float v0 = __ldg(w + (size_t)(2 * k2) * ld + coff + n);
        float v1 = __ldg(w + (size_t)(2 * k2 + 1) * ld + coff + n);
        u32 H, L; bsplit(v0, v1, H, L);
        bHi[n * RS + k2] = H;
        bLo[n * RS + k2] = L;
    }
}

// ===================== Kernel: bf16 HMMA MLP -> mix =====================
__global__ void __launch_bounds__(TPB_A, 2)
mlp_tc_kernel(const float* __restrict__ radial,
              const float* __restrict__ w1, const float* __restrict__ w2,
              const float* __restrict__ w3, const float* __restrict__ w4,
              int n_edges)
{
    extern __shared__ u32 smu[];
    u32* aHi = smu;
    u32* aLo = smu + 4608;
    u32* bHi = smu + 9216;
    u32* bLo = smu + 11520;

    int tid = threadIdx.x;
    int warp = tid >> 5, lane = tid & 31;
    int gid = lane >> 2, tig = lane & 3;
    int m0 = (warp & 3) * 32;
    int n0 = (warp >> 2) * 32;
    int e0 = blockIdx.x * TE;

    if (tid < 128) {
        int ge = e0 + tid;
        float4 a = make_float4(0,0,0,0), b = make_float4(0,0,0,0);
        if (ge < n_edges) {
            const float4* rp = (const float4*)(radial + (size_t)ge * 8);
            a = __ldg(rp); b = __ldg(rp + 1);
        }
        int r = tid * RS;
        u32 H, L;
        bsplit(a.x, a.y, H, L); aHi[r + 0] = H; aLo[r + 0] = L;
        bsplit(a.z, a.w, H, L); aHi[r + 1] = H; aLo[r + 1] = L;
        bsplit(b.x, b.y, H, L); aHi[r + 2] = H; aLo[r + 2] = L;
        bsplit(b.z, b.w, H, L); aHi[r + 3] = H; aLo[r + 3] = L;
        #pragma unroll
        for (int k2 = 4; k2 < 8; k2++) { aHi[r + k2] = 0; aLo[r + k2] = 0; }
    } else {
        int t = tid - 128;
        #pragma unroll
        for (int i = 0; i < 4; i++) {
            int idx = t + i * 128;
            int n = idx & 63, k2 = idx >> 6;
            float v0 = 0.f, v1 = 0.f;
            if (k2 < 4) {
                v0 = __ldg(w1 + (size_t)(2 * k2) * 64 + n);
                v1 = __ldg(w1 + (size_t)(2 * k2 + 1) * 64 + n);
            }
            u32 H, L; bsplit(v0, v1, H, L);
            bHi[n * RS + k2] = H;
            bLo[n * RS + k2] = L;
        }
    }
    __syncthreads();

    float d[2][4][4];

    wgemm<1>(smu, m0, n0, gid, tig, d);
    __syncthreads();
    epi(d, 0.35355339059327373f, 1.0f, aHi, aLo, m0, n0, gid, tig);
    stageW64(w2, 64, 0, bHi, bLo, tid);
    __syncthreads();

    wgemm<4>(smu, m0, n0, gid, tig, d);
    __syncthreads();
    epi(d, 0.125f, 1.0f, aHi, aLo, m0, n0, gid, tig);
    stageW64(w3, 64, 0, bHi, bLo, tid);
    __syncthreads();

    wgemm<4>(smu, m0, n0, gid, tig, d);
    __syncthreads();
    epi(d, 0.125f, 0.03125f, aHi, aLo, m0, n0, gid, tig);
    stageW64(w4, 256, 0, bHi, bLo, tid);
    __syncthreads();

    #pragma unroll 1
    for (int c = 0; c < 4; c++) {
        wgemm<4>(smu, m0, n0, gid, tig, d);
        #pragma unroll
        for (int mt = 0; mt < 2; mt++) {
            int er0 = e0 + m0 + mt * 16 + gid;
            int er1 = er0 + 8;
            #pragma unroll
            for (int nt = 0; nt < 4; nt++) {
                int col = c * 64 + n0 + nt * 8 + 2 * tig;
                if (er0 < n_edges)
                    *(float2*)&g_mix[(size_t)er0 * 256 + col] =
                        make_float2(d[mt][nt][0], d[mt][nt][1]);
                if (er1 < n_edges)
                    *(float2*)&g_mix[(size_t)er1 * 256 + col] =
                        make_float2(d[mt][nt][2], d[mt][nt][3]);
            }
        }
        if (c < 3) {
            __syncthreads();
            stageW64(w4, 256, (c + 1) * 64, bHi, bLo, tid);
            __syncthreads();
        }
    }
}

// ===================== CSR build =====================
__global__ void count_kernel(const int* __restrict__ receivers, int n_edges) {
    int e = blockIdx.x * 256 + threadIdx.x;
    if (e < n_edges) atomicAdd(&g_cnt[__ldg(receivers + e)], 1);
}

#define SCAN_T 256
__global__ void scan_kernel(int n_nodes) {
    __shared__ int part[SCAN_T];
    int tid = threadIdx.x;
    int chunk = (n_nodes + SCAN_T - 1) / SCAN_T;
    int base = tid * chunk;
    int s = 0;
    for (int i = 0; i < chunk; i++) {
        int idx = base + i;
        if (idx < n_nodes) s += g_cnt[idx];
    }
    part[tid] = s;
    __syncthreads();
    #pragma unroll
    for (int off = 1; off < SCAN_T; off <<= 1) {
        int v = (tid >= off) ? part[tid - off] : 0;
        __syncthreads();
        part[tid] += v;
        __syncthreads();
    }
    int run = (tid == 0) ? 0 : part[tid - 1];
    for (int i = 0; i < chunk; i++) {
        int idx = base + i;
        if (idx < n_nodes) {
            g_rowptr[idx] = run;
            g_cur[idx] = run;
            run += g_cnt[idx];
        }
    }
    if (tid == SCAN_T - 1) g_rowptr[n_nodes] = run;
}

__global__ void fill_kernel(const int* __restrict__ receivers, int n_edges) {
    int e = blockIdx.x * 256 + threadIdx.x;
    if (e < n_edges) {
        int pos = atomicAdd(&g_cur[__ldg(receivers + e)], 1);
        g_elist[pos] = e;
    }
}

// ===================== channel-major gather: registers only, no atomics =====================
#define TPB_G 256

__global__ void __launch_bounds__(TPB_G)
gather_kernel(const float* __restrict__ vectors,
              const float* __restrict__ node_feats,
              const int* __restrict__ senders,
              float* __restrict__ out, int n_nodes)
{
    int warp = threadIdx.x >> 5, lane = threadIdx.x & 31;
    int n = blockIdx.x * (TPB_G / 32) + warp;
    if (n >= n_nodes) return;

    const int c2 = lane * 2;       // this lane owns channels c2, c2+1

    float a0[2]  = {0.f, 0.f};
    float a1[6]  = {0.f, 0.f, 0.f, 0.f, 0.f, 0.f};
    float a2[10] = {0.f, 0.f, 0.f, 0.f, 0.f, 0.f, 0.f, 0.f, 0.f, 0.f};
    float a3[14] = {0.f, 0.f, 0.f, 0.f, 0.f, 0.f, 0.f,
                    0.f, 0.f, 0.f, 0.f, 0.f, 0.f, 0.f};

    int beg = g_rowptr[n], end = g_rowptr[n + 1];

    #pragma unroll 4
    for (int i = beg; i < end; i++) {
        int e = g_elist[i];
        int snd = __ldg(senders + e);
        const float* mrow = g_mix + (size_t)e * 256;
        float2 m0 = *(const float2*)(mrow + c2);
        float2 m1 = *(const float2*)(mrow + 64 + c2);
        float2 m2 = *(const float2*)(mrow + 128 + c2);
        float2 m3 = *(const float2*)(mrow + 192 + c2);
        float2 s  = __ldg((const float2*)(node_feats + (size_t)snd * 64 + c2));

        // spherical harmonics (broadcast loads; computed per lane in regs)
        float vx = __ldg(vectors + 3 * (size_t)e + 0);
        float vy = __ldg(vectors + 3 * (size_t)e + 1);
        float vz = __ldg(vectors + 3 * (size_t)e + 2);
        float inv = rsqrtf(vx*vx + vy*vy + vz*vz);
        float x = vx*inv, y = vy*inv, z = vz*inv;
        const float s3  = 1.7320508075688772f;
        const float s5  = 2.23606797749979f;
        const float s15 = 3.872983346207417f;
        const float c33 = 2.091650066335189f;
        const float c32 = 10.246950765959598f;
        const float c31 = 1.6201851746019651f;
        const float c30 = 1.3228756555322954f;
        float z2 = z*z, x2 = x*x, y2 = y*y;
        float yv[15];
        yv[0]  = s3 * y;  yv[1] = s3 * z;  yv[2] = s3 * x;
        yv[3]  = s15 * x * y;
        yv[4]  = s15 * y * z;
        yv[5]  = 0.5f * s5 * (3.0f * z2 - 1.0f);
        yv[6]  = s15 * x * z;
        yv[7]  = 0.5f * s15 * (x2 - y2);
        yv[8]  = c33 * y * (3.0f * x2 - y2);
        yv[9]  = c32 * x * y * z;
        yv[10] = c31 * y * (5.0f * z2 - 1.0f);
        yv[11] = c30 * z * (5.0f * z2 - 3.0f);
        yv[12] = c31 * x * (5.0f * z2 - 1.0f);
        yv[13] = 0.5f * c32 * z * (x2 - y2);
        yv[14] = c33 * x * (x2 - 3.0f * y2);

        // tensor product, all in registers
        float t0a = m0.x * s.x, t0b = m0.y * s.y;
        a0[0] += t0a; a0[1] += t0b;

        float t1a = m1.x * s.x, t1b = m1.y * s.y;
        #pragma unroll
        for (int k = 0; k < 3; k++) {
            a1[k]     += t1a * yv[k];
            a1[3 + k] += t1b * yv[k];
        }
        float t2a = m2.x * s.x, t2b = m2.y * s.y;
        #pragma unroll
        for (int k = 0; k < 5; k++) {
            a2[k]     += t2a * yv[3 + k];
            a2[5 + k] += t2b * yv[3 + k];
        }
        float t3a = m3.x * s.x, t3b = m3.y * s.y;
        #pragma unroll
        for (int k = 0; k < 7; k++) {
            a3[k]     += t3a * yv[8 + k];
            a3[7 + k] += t3b * yv[8 + k];
        }
    }

    // store: per-lane contiguous runs, each row written exactly once
    float* ob = out + (size_t)n * 1024;
    *(float2*)(ob + c2) = make_float2(a0[0], a0[1]);
    float* p1 = ob + 64 + 3 * c2;
    *(float2*)(p1 + 0) = make_float2(a1[0], a1[1]);
    *(float2*)(p1 + 2) = make_float2(a1[2], a1[3]);
    *(float2*)(p1 + 4) = make_float2(a1[4], a1[5]);
    float* p2 = ob + 256 + 5 * c2;
    #pragma unroll
    for (int q = 0; q < 5; q++)
        *(float2*)(p2 + 2 * q) = make_float2(a2[2*q], a2[2*q + 1]);
    float* p3 = ob + 576 + 7 * c2;
    #pragma unroll
    for (int q = 0; q < 7; q++)
        *(float2*)(p3 + 2 * q) = make_float2(a3[2*q], a3[2*q + 1]);
}

extern "C" void kernel_launch(void* const* d_in, const int* in_sizes, int n_in,
                              void* d_out, int out_size)
{
    const float* vectors    = (const float*)d_in[0];
    const float* node_feats = (const float*)d_in[1];
    const float* radial     = (const float*)d_in[2];
    const float* w1         = (const float*)d_in[3];
    const float* w2         = (const float*)d_in[4];
    const float* w3         = (const float*)d_in[5];
    const float* w4         = (const float*)d_in[6];
    const int*   senders    = (const int*)d_in[7];
    const int*   receivers  = (const int*)d_in[8];
    float* out = (float*)d_out;

    int n_edges = in_sizes[7];
    int n_nodes = out_size / 1024;

    static void* cnt_addr = nullptr;
    static cudaStream_t s2 = nullptr;
    static cudaEvent_t evFork, evCsr;
    if (cnt_addr == nullptr) {
        cudaGetSymbolAddress(&cnt_addr, g_cnt);
        cudaStreamCreateWithFlags(&s2, cudaStreamNonBlocking);
        cudaEventCreateWithFlags(&evFork, cudaEventDisableTiming);
        cudaEventCreateWithFlags(&evCsr, cudaEventDisableTiming);
    }

    cudaFuncSetAttribute(mlp_tc_kernel,
                         cudaFuncAttributeMaxDynamicSharedMemorySize,
                         SMEM_U32 * sizeof(u32));

    // fork: CSR build on s2 runs concurrently with mlp on the origin stream
    cudaEventRecord(evFork, 0);
    cudaStreamWaitEvent(s2, evFork, 0);

    cudaMemsetAsync(cnt_addr, 0, (size_t)n_nodes * sizeof(int), s2);
    int eg = (n_edges + 255) / 256;
    count_kernel<<<eg, 256, 0, s2>>>(receivers, n_edges);
    scan_kernel<<<1, SCAN_T, 0, s2>>>(n_nodes);
    fill_kernel<<<eg, 256, 0, s2>>>(receivers, n_edges);
    cudaEventRecord(evCsr, s2);

    int grid_a = (n_edges + TE - 1) / TE;
    mlp_tc_kernel<<<grid_a, TPB_A, SMEM_U32 * sizeof(u32)>>>(
        radial, w1, w2, w3, w4, n_edges);

    // join: gather needs both mlp (same stream) and the CSR build
    cudaStreamWaitEvent(0, evCsr, 0);
    int npb = TPB_G / 32;
    int grid_g = (n_nodes + npb - 1) / npb;
    gather_kernel<<<grid_g, TPB_G>>>(vectors, node_feats, senders, out, n_nodes);
}